// round 1
// baseline (speedup 1.0000x reference)
#include <cuda_runtime.h>
#include <cstdint>

// CognitiveLorenzField: vL stays parallel to vL0, vJ stays in span{vL0, vJ0}.
// Entire 500-step dynamics reduces to a scalar recurrence (a,b,c) driven by
// the Lorenz z. Output = rank-1 / rank-2 expansions -> pure store bandwidth.

#define DIM       65536
#define STEPS     500
#define CHUNK     10
#define TCHUNKS   (STEPS / CHUNK)     // 50
#define IBLK      64                  // i-slices of 1024 floats
#define NTHREADS  256

__device__ float4 g_abc4[STEPS];      // (a, b, c, z) per step, published by producer
__device__ int    g_step;             // number of completed steps (release-published)

__global__ void clf_reset_kernel() { g_step = 0; }

__global__ __launch_bounds__(NTHREADS)
void clf_kernel(const float* __restrict__ vL,
                const float* __restrict__ vJ,
                float* __restrict__ out)
{
    const float dt = 0.01f;

    if (blockIdx.x == 0) {
        // ---------------- Producer block ----------------
        __shared__ float sP[NTHREADS];
        __shared__ float sQ[NTHREADS];
        const float4* vL4 = (const float4*)vL;
        const float4* vJ4 = (const float4*)vJ;

        float p = 0.0f, q = 0.0f;
        for (int k = threadIdx.x; k < DIM / 4; k += NTHREADS) {
            float4 l = vL4[k];
            float4 j = vJ4[k];
            p += l.x * l.x + l.y * l.y + l.z * l.z + l.w * l.w;
            q += l.x * j.x + l.y * j.y + l.z * j.z + l.w * j.w;
        }
        sP[threadIdx.x] = p;
        sQ[threadIdx.x] = q;
        __syncthreads();
        for (int off = NTHREADS / 2; off > 0; off >>= 1) {
            if (threadIdx.x < off) {
                sP[threadIdx.x] += sP[threadIdx.x + off];
                sQ[threadIdx.x] += sQ[threadIdx.x + off];
            }
            __syncthreads();
        }

        if (threadIdx.x == 0) {
            const float P = sP[0];
            const float Q = sQ[0];
            float x = 1.0f, y = 1.0f, z = 1.0f;
            float a = 1.0f, b = 0.0f, c = 1.0f;   // vL = a*vL0 ; vJ = b*vL0 + c*vJ0
            float* out_z = out + 2ull * STEPS * DIM;

            for (int t = 0; t < STEPS; t++) {
                // Lorenz Euler step (matches reference op order)
                float dx = 10.0f * (y - x);
                float dy = x * (28.0f - z) - y;
                float dz = x * y - (float)(8.0 / 3.0) * z;
                x += dt * dx;
                y += dt * dy;
                z += dt * dz;
                float alpha = 1.0f + 0.5f * z;

                // scalarized vector dynamics
                float dot = a * (b * P + c * Q);
                float nsq = a * a * P + 1e-8f;
                float r   = dot / nsq;

                float an = a + dt * (alpha * ((r - 1.0f) * a) + 0.2f * a);
                float bn = b + dt * (alpha * (r * a - b) + 0.2f * (a - b));
                float cn = c + dt * (alpha * (-c) + 0.2f * (-c));
                a = an; b = bn; c = cn;

                g_abc4[t] = make_float4(a, b, c, z);
                out_z[t]  = z;

                if (((t + 1) % CHUNK) == 0) {
                    __threadfence();                 // publish table entries
                    atomicExch(&g_step, t + 1);      // then advance the flag
                }
            }
            __threadfence();
            atomicExch(&g_step, STEPS);
        }
        return;
    }

    // ---------------- Writer blocks ----------------
    int w     = blockIdx.x - 1;
    int chunk = w / IBLK;               // t-chunk (chunk-major: early chunks in wave 1)
    int ib    = w % IBLK;               // i-slice
    int t0    = chunk * CHUNK;
    int f4    = ib * NTHREADS + threadIdx.x;   // float4 index into the vectors

    const float4* vL4 = (const float4*)vL;
    const float4* vJ4 = (const float4*)vJ;
    float4 l = __ldg(vL4 + f4);         // fetch operands while we wait
    float4 j = __ldg(vJ4 + f4);

    if (threadIdx.x == 0) {
        const int need = t0 + CHUNK;
        while (true) {
            int s = atomicAdd(&g_step, 0);
            if (s >= need) break;
            __nanosleep(128);
        }
        __threadfence();                 // acquire before table reads
    }
    __syncthreads();

    float4* outL4 = (float4*)out;
    float4* outJ4 = ((float4*)out) + (size_t)STEPS * (DIM / 4);

    #pragma unroll
    for (int tt = 0; tt < CHUNK; tt++) {
        int t = t0 + tt;
        float4 s = __ldcg(&g_abc4[t]);   // L2 load: coherent with producer's fence
        float a = s.x, b = s.y, c = s.z;

        float4 oL = make_float4(a * l.x, a * l.y, a * l.z, a * l.w);
        float4 oJ = make_float4(fmaf(b, l.x, c * j.x),
                                fmaf(b, l.y, c * j.y),
                                fmaf(b, l.z, c * j.z),
                                fmaf(b, l.w, c * j.w));

        size_t base = (size_t)t * (DIM / 4) + f4;
        __stcs(&outL4[base], oL);        // streaming stores: 262 MB, don't thrash L2
        __stcs(&outJ4[base], oJ);
    }
}

extern "C" void kernel_launch(void* const* d_in, const int* in_sizes, int n_in,
                              void* d_out, int out_size)
{
    const float* vL = (const float*)d_in[0];
    const float* vJ = (const float*)d_in[1];
    float* out = (float*)d_out;

    clf_reset_kernel<<<1, 1>>>();
    clf_kernel<<<1 + IBLK * TCHUNKS, NTHREADS>>>(vL, vJ, out);
}

// round 2
// speedup vs baseline: 1.5680x; 1.5680x over previous
#include <cuda_runtime.h>
#include <cstdint>

// CognitiveLorenzField: vL stays parallel to vL0, vJ stays in span{vL0,vJ0}.
// 500-step dynamics collapses to a scalar recurrence (a,b,c) driven by the
// Lorenz z. Output is rank-1/rank-2 expansion -> pure store bandwidth.
//
// Pipeline: pre-kernel (deterministic P,Q partials + flag reset) ->
// fused kernel: block 0 = scalar producer publishing per-chunk flags,
// 592 persistent writer blocks streaming 262 MB of float4 stores.

#define DIM       65536
#define STEPS     500
#define CHUNK     10
#define TCHUNKS   (STEPS / CHUNK)       // 50
#define IBLK      64                    // i-slices of 1024 floats
#define NTILES    (TCHUNKS * IBLK)      // 3200
#define NT        256
#define WRITERS   592                   // persistent writer blocks (~4 CTA/SM)
#define RBLK      64                    // reduction blocks

__device__ float4 g_tab[STEPS];         // (a, b, c, z) per step
__device__ int    g_flag[TCHUNKS];      // per-chunk ready flags
__device__ float  g_pP[RBLK], g_pQ[RBLK];

// ---- pre-kernel: per-block deterministic partial dots + flag reset ----
__global__ __launch_bounds__(NT)
void clf_pre(const float* __restrict__ vL, const float* __restrict__ vJ)
{
    const float4* vL4 = (const float4*)vL;
    const float4* vJ4 = (const float4*)vJ;
    int b = blockIdx.x;
    int k = b * NT + threadIdx.x;       // one float4 per thread, 1024 floats/block

    float4 l = vL4[k];
    float4 j = vJ4[k];
    float p = l.x * l.x + l.y * l.y + l.z * l.z + l.w * l.w;
    float q = l.x * j.x + l.y * j.y + l.z * j.z + l.w * j.w;

    #pragma unroll
    for (int off = 16; off > 0; off >>= 1) {
        p += __shfl_down_sync(0xffffffffu, p, off);
        q += __shfl_down_sync(0xffffffffu, q, off);
    }
    __shared__ float sp[8], sq[8];
    int wid = threadIdx.x >> 5, lid = threadIdx.x & 31;
    if (lid == 0) { sp[wid] = p; sq[wid] = q; }
    __syncthreads();
    if (threadIdx.x == 0) {
        float P = 0.0f, Q = 0.0f;
        #pragma unroll
        for (int i = 0; i < 8; i++) { P += sp[i]; Q += sq[i]; }
        g_pP[b] = P;
        g_pQ[b] = Q;
    }
    if (b == 0 && threadIdx.x < TCHUNKS)
        g_flag[threadIdx.x] = 0;        // re-arm for this graph replay
}

// ---- fused producer + persistent writers ----
__global__ __launch_bounds__(NT)
void clf_main(const float* __restrict__ vL,
              const float* __restrict__ vJ,
              float* __restrict__ out)
{
    const float dt = 0.01f;

    if (blockIdx.x == 0) {
        // -------- producer (single thread scalar recurrence) --------
        if (threadIdx.x == 0) {
            float P = 0.0f, Q = 0.0f;
            #pragma unroll
            for (int i = 0; i < RBLK; i++) { P += g_pP[i]; Q += g_pQ[i]; }

            float x = 1.0f, y = 1.0f, z = 1.0f;
            float a = 1.0f, b = 0.0f, c = 1.0f;  // vL=a*vL0 ; vJ=b*vL0+c*vJ0
            float* out_z = out + 2ull * STEPS * DIM;

            for (int t = 0; t < STEPS; t++) {
                // Lorenz Euler step (reference op order)
                float dx = 10.0f * (y - x);
                float dy = x * (28.0f - z) - y;
                float dz = x * y - (float)(8.0 / 3.0) * z;
                x += dt * dx;
                y += dt * dy;
                z += dt * dz;
                float alpha = 1.0f + 0.5f * z;

                // scalarized vector dynamics
                float dot = a * (b * P + c * Q);
                float nsq = a * a * P + 1e-8f;
                float r   = __fdividef(dot, nsq);

                float an = a + dt * (alpha * ((r - 1.0f) * a) + 0.2f * a);
                float bn = b + dt * (alpha * (r * a - b) + 0.2f * (a - b));
                float cn = c + dt * (alpha * (-c) + 0.2f * (-c));
                a = an; b = bn; c = cn;

                g_tab[t] = make_float4(a, b, c, z);
                out_z[t] = z;

                if (((t + 1) % CHUNK) == 0) {
                    __threadfence();                       // publish table
                    ((volatile int*)g_flag)[t / CHUNK] = 1;
                }
            }
        }
        return;
    }

    // -------- persistent writers --------
    int w = blockIdx.x - 1;
    const float4* vL4 = (const float4*)vL;
    const float4* vJ4 = (const float4*)vJ;
    float4* outL4 = (float4*)out;
    float4* outJ4 = outL4 + (size_t)STEPS * (DIM / 4);

    for (int tt = w; tt < NTILES; tt += WRITERS) {
        int chunk = tt >> 6;            // tile order is chunk-major
        int slice = tt & (IBLK - 1);
        int f4    = slice * NT + threadIdx.x;

        float4 l = __ldg(vL4 + f4);     // L2-hot after first touch
        float4 j = __ldg(vJ4 + f4);

        if (threadIdx.x == 0) {
            while (((volatile int*)g_flag)[chunk] == 0)
                __nanosleep(256);
            __threadfence();            // acquire
        }
        __syncthreads();

        #pragma unroll
        for (int u = 0; u < CHUNK; u++) {
            int t = chunk * CHUNK + u;
            float4 s = __ldcg(&g_tab[t]);
            float a = s.x, b = s.y, c = s.z;

            float4 oL = make_float4(a * l.x, a * l.y, a * l.z, a * l.w);
            float4 oJ = make_float4(fmaf(b, l.x, c * j.x),
                                    fmaf(b, l.y, c * j.y),
                                    fmaf(b, l.z, c * j.z),
                                    fmaf(b, l.w, c * j.w));

            size_t base = (size_t)t * (DIM / 4) + f4;
            __stcs(&outL4[base], oL);   // streaming stores, bypass L2 persistence
            __stcs(&outJ4[base], oJ);
        }
    }
}

extern "C" void kernel_launch(void* const* d_in, const int* in_sizes, int n_in,
                              void* d_out, int out_size)
{
    const float* vL = (const float*)d_in[0];
    const float* vJ = (const float*)d_in[1];
    float* out = (float*)d_out;

    clf_pre<<<RBLK, NT>>>(vL, vJ);
    clf_main<<<1 + WRITERS, NT>>>(vL, vJ, out);
}